// round 1
// baseline (speedup 1.0000x reference)
#include <cuda_runtime.h>
#include <cuda_bf16.h>
#include <cstdint>

// Problem constants (shapes fixed by the dataset)
#define N_NODES_MAX 100000
#define D 64
#define OUT 64
#define LN_EPS 1e-5f

// Scratch: neighbor_sum accumulator [N, D] — device global (no allocs allowed)
__device__ float g_nsum[N_NODES_MAX * D];
__device__ int g_is64;  // 1 if edge_index is int64, 0 if int32

// ---------------------------------------------------------------------------
// Kernel 0a: detect edge_index dtype. If the data is really int32 pairs read
// as int64, high halves are the *next* index (~uniform in [0,N)), which is 0
// with prob 1e-5 per word -> scanning 256 words misdetects with prob ~1e-1280.
// ---------------------------------------------------------------------------
__global__ void detect_dtype_kernel(const long long* __restrict__ ei,
                                    int n_words, int n_nodes) {
    if (blockIdx.x == 0 && threadIdx.x == 0) {
        int is64 = 1;
        int lim = n_words < 256 ? n_words : 256;
        for (int i = 0; i < lim; i++) {
            long long v = ei[i];
            if (v < 0 || v >= (long long)n_nodes) { is64 = 0; break; }
        }
        g_is64 = is64;
    }
}

// ---------------------------------------------------------------------------
// Kernel 0b: zero the accumulator (graph-replayable; must re-zero every call)
// ---------------------------------------------------------------------------
__global__ void zero_kernel(int n_float4) {
    int i = blockIdx.x * blockDim.x + threadIdx.x;
    int stride = gridDim.x * blockDim.x;
    float4* p = reinterpret_cast<float4*>(g_nsum);
    float4 z = make_float4(0.f, 0.f, 0.f, 0.f);
    for (; i < n_float4; i += stride) p[i] = z;
}

// ---------------------------------------------------------------------------
// Kernel 1: scatter-add.  One warp per edge (grid-stride).
// Lane l handles floats [2l, 2l+1] via float2 load + red.global.add.v2.f32.
// x row gather: 32 lanes x 8B = 256B, fully coalesced (2 sectors... 8 sectors).
// ---------------------------------------------------------------------------
__global__ void scatter_kernel(const float2* __restrict__ x2,
                               const void* __restrict__ ei_raw,
                               int n_edges) {
    const int lane = threadIdx.x & 31;
    int warp = (blockIdx.x * blockDim.x + threadIdx.x) >> 5;
    const int nwarps = (gridDim.x * blockDim.x) >> 5;
    const int is64 = g_is64;
    float2* __restrict__ nsum2 = reinterpret_cast<float2*>(g_nsum);

    const long long* ei64 = reinterpret_cast<const long long*>(ei_raw);
    const int*       ei32 = reinterpret_cast<const int*>(ei_raw);

    for (int e = warp; e < n_edges; e += nwarps) {
        long long row, col;
        if (is64) {
            row = ei64[e];
            col = ei64[n_edges + e];
        } else {
            row = ei32[e];
            col = ei32[n_edges + e];
        }
        float2 v = x2[row * 32 + lane];
        float2* dst = &nsum2[col * 32 + lane];
        asm volatile("red.global.add.v2.f32 [%0], {%1, %2};"
                     :: "l"(dst), "f"(v.x), "f"(v.y) : "memory");
    }
}

// ---------------------------------------------------------------------------
// Kernel 2: fused concat + Linear(128->64) + bias + LayerNorm.
// Warp-per-node. W (128x64 f32 = 32KB) staged in shared as float2 rows.
// Input row (128 f32) staged in per-warp shared; broadcast LDS is free.
// Lane l owns outputs {2l, 2l+1}. LN via warp shuffle reduction.
// ---------------------------------------------------------------------------
__global__ void __launch_bounds__(256) gemm_ln_kernel(
    const float* __restrict__ x,
    const float* __restrict__ W,
    const float* __restrict__ b,
    const float* __restrict__ gamma,
    const float* __restrict__ beta,
    float* __restrict__ out,
    int n_nodes) {

    __shared__ float2 Wsh[128 * 32];       // [k][j2] : W[k][2j], W[k][2j+1]
    __shared__ float  in_sh[8][128];       // per-warp input row

    const int tid  = threadIdx.x;
    const int lane = tid & 31;
    const int w    = tid >> 5;

    // cooperative W load (linear copy: row-major [128][64] == float2 [128][32])
    const float2* W2 = reinterpret_cast<const float2*>(W);
    #pragma unroll
    for (int i = tid; i < 128 * 32; i += 256) Wsh[i] = W2[i];
    __syncthreads();

    const float2 bias = reinterpret_cast<const float2*>(b)[lane];
    const float2 gam  = reinterpret_cast<const float2*>(gamma)[lane];
    const float2 bet  = reinterpret_cast<const float2*>(beta)[lane];

    const float2* __restrict__ nsum2 = reinterpret_cast<const float2*>(g_nsum);
    const float2* __restrict__ x2    = reinterpret_cast<const float2*>(x);
    float2* __restrict__ out2        = reinterpret_cast<float2*>(out);

    int node = (blockIdx.x * blockDim.x + tid) >> 5;
    const int nwarps = (gridDim.x * blockDim.x) >> 5;

    for (; node < n_nodes; node += nwarps) {
        // stage concat(x[node], nsum[node]) into shared
        float2 t0 = x2[(long long)node * 32 + lane];
        float2 t1 = nsum2[(long long)node * 32 + lane];
        in_sh[w][2 * lane]          = t0.x;
        in_sh[w][2 * lane + 1]      = t0.y;
        in_sh[w][64 + 2 * lane]     = t1.x;
        in_sh[w][64 + 2 * lane + 1] = t1.y;
        __syncwarp();

        float2 acc = make_float2(0.f, 0.f);
        #pragma unroll 8
        for (int k = 0; k < 128; k++) {
            float a = in_sh[w][k];            // broadcast (conflict-free)
            float2 wv = Wsh[k * 32 + lane];   // stride-1 float2 (conflict-free)
            acc.x = fmaf(a, wv.x, acc.x);
            acc.y = fmaf(a, wv.y, acc.y);
        }
        acc.x += bias.x;
        acc.y += bias.y;

        // LayerNorm over 64 outputs (population variance, matches jnp.var)
        float s  = acc.x + acc.y;
        float ss = acc.x * acc.x + acc.y * acc.y;
        #pragma unroll
        for (int m = 16; m > 0; m >>= 1) {
            s  += __shfl_xor_sync(0xFFFFFFFFu, s,  m);
            ss += __shfl_xor_sync(0xFFFFFFFFu, ss, m);
        }
        const float inv64 = 1.0f / 64.0f;
        float mu  = s * inv64;
        float var = ss * inv64 - mu * mu;
        float rs  = rsqrtf(var + LN_EPS);

        float2 o;
        o.x = (acc.x - mu) * rs * gam.x + bet.x;
        o.y = (acc.y - mu) * rs * gam.y + bet.y;
        out2[(long long)node * 32 + lane] = o;
        __syncwarp();  // protect in_sh before next iteration's writes
    }
}

// ---------------------------------------------------------------------------
// launch
// ---------------------------------------------------------------------------
extern "C" void kernel_launch(void* const* d_in, const int* in_sizes, int n_in,
                              void* d_out, int out_size) {
    const float* x     = (const float*)d_in[0];
    const void*  ei    = d_in[1];
    const float* W     = (const float*)d_in[2];
    const float* b     = (const float*)d_in[3];
    const float* gamma = (const float*)d_in[4];
    const float* beta  = (const float*)d_in[5];
    float* out = (float*)d_out;

    const int n_nodes = in_sizes[0] / D;      // 100000
    const int n_edges = in_sizes[1] / 2;      // 1000000

    // 0a: dtype detection (reads min(256, n_edges/... ) int64 words; safe:
    //     2*n_edges int32 elements >= 256 int64 words when n_edges >= 256)
    int n_words = n_edges / 2;  // conservative lower bound on available int64 words
    if (n_words > 256) n_words = 256;
    detect_dtype_kernel<<<1, 32>>>((const long long*)ei, n_words, n_nodes);

    // 0b: zero accumulator
    const int n_f4 = n_nodes * D / 4;
    zero_kernel<<<1184, 256>>>(n_f4);

    // 1: scatter  (2368 blocks x 256 = 18944 warps, ~53 edges/warp)
    scatter_kernel<<<2368, 256>>>((const float2*)x, ei, n_edges);

    // 2: fused GEMM + LayerNorm (warp-per-node; 12500 blocks covers 100k nodes)
    int gemm_blocks = (n_nodes + 7) / 8;
    gemm_ln_kernel<<<gemm_blocks, 256>>>(x, W, b, gamma, beta, out, n_nodes);
}

// round 2
// speedup vs baseline: 1.6890x; 1.6890x over previous
#include <cuda_runtime.h>
#include <cuda_bf16.h>
#include <cstdint>

// Problem constants (shapes fixed by the dataset)
#define N_NODES_MAX 100000
#define D 64
#define OUT 64
#define LN_EPS 1e-5f

// Scratch: neighbor_sum accumulator [N, D] — device global (no allocs allowed)
__device__ __align__(16) float g_nsum[N_NODES_MAX * D];
__device__ int g_is64;  // 1 if edge_index is int64, 0 if int32

// ---------------------------------------------------------------------------
// Kernel 0a: detect edge_index dtype. If the data is really int32 pairs read
// as int64, high halves are the *next* index (~uniform in [0,N)), which is 0
// with prob 1e-5 per word -> scanning 256 words misdetects with prob ~1e-1280.
// ---------------------------------------------------------------------------
__global__ void detect_dtype_kernel(const long long* __restrict__ ei,
                                    int n_words, int n_nodes) {
    if (blockIdx.x == 0 && threadIdx.x == 0) {
        int is64 = 1;
        int lim = n_words < 256 ? n_words : 256;
        for (int i = 0; i < lim; i++) {
            long long v = ei[i];
            if (v < 0 || v >= (long long)n_nodes) { is64 = 0; break; }
        }
        g_is64 = is64;
    }
}

// ---------------------------------------------------------------------------
// Kernel 0b: zero the accumulator (graph-replayable; must re-zero every call)
// ---------------------------------------------------------------------------
__global__ void zero_kernel(int n_float4) {
    int i = blockIdx.x * blockDim.x + threadIdx.x;
    int stride = gridDim.x * blockDim.x;
    float4* p = reinterpret_cast<float4*>(g_nsum);
    float4 z = make_float4(0.f, 0.f, 0.f, 0.f);
    for (; i < n_float4; i += stride) p[i] = z;
}

// ---------------------------------------------------------------------------
// Kernel 1: scatter-add.  One warp per edge (grid-stride).
// Lane l handles floats [2l, 2l+1] via float2 load + red.global.add.v2.f32.
// ---------------------------------------------------------------------------
__global__ void scatter_kernel(const float2* __restrict__ x2,
                               const void* __restrict__ ei_raw,
                               int n_edges) {
    const int lane = threadIdx.x & 31;
    int warp = (blockIdx.x * blockDim.x + threadIdx.x) >> 5;
    const int nwarps = (gridDim.x * blockDim.x) >> 5;
    const int is64 = g_is64;
    float2* __restrict__ nsum2 = reinterpret_cast<float2*>(g_nsum);

    const long long* ei64 = reinterpret_cast<const long long*>(ei_raw);
    const int*       ei32 = reinterpret_cast<const int*>(ei_raw);

    for (int e = warp; e < n_edges; e += nwarps) {
        long long row, col;
        if (is64) {
            row = ei64[e];
            col = ei64[n_edges + e];
        } else {
            row = ei32[e];
            col = ei32[n_edges + e];
        }
        float2 v = x2[row * 32 + lane];
        float2* dst = &nsum2[col * 32 + lane];
        asm volatile("red.global.add.v2.f32 [%0], {%1, %2};"
                     :: "l"(dst), "f"(v.x), "f"(v.y) : "memory");
    }
}

// ---------------------------------------------------------------------------
// Kernel 2: fused concat + Linear(128->64) + bias + LayerNorm.
// Register-tiled GEMM: block = 64 nodes x 64 outs, 256 threads,
// thread tile = 4 nodes x 4 outs, K = 128.
// A staged transposed [k][n] in shared (32KB); W staged as-is (32KB) and read
// as natural f32x2 pairs over the OUT dimension. Inner loop per k per thread:
//   1x LDS.128 (a: 4 nodes, broadcast)  +  1x LDS.128 (w: 2 f32x2 pairs)
//   4x mov.b64 {a,a}                    +  8x fma.rn.f32x2  (16 FMA lanes)
// LayerNorm via 4-round shfl.xor over the 16 tx lanes.
// ---------------------------------------------------------------------------
#define TILE_N 64

__global__ void __launch_bounds__(256) gemm_ln_kernel(
    const float4* __restrict__ x4,
    const float*  __restrict__ W,
    const float*  __restrict__ b,
    const float*  __restrict__ gamma,
    const float*  __restrict__ beta,
    float4* __restrict__ out4,
    int n_nodes) {

    extern __shared__ char smem_raw[];
    float* Ash = reinterpret_cast<float*>(smem_raw);                // [128][64]
    unsigned long long* Wp =
        reinterpret_cast<unsigned long long*>(smem_raw + 128 * 64 * 4); // [128][32] f32x2 pairs

    const int tid = threadIdx.x;
    const int tx  = tid & 15;   // out-pair group: pairs {2tx, 2tx+1} -> outs 4tx..4tx+3
    const int ty  = tid >> 4;   // node group: nodes 4ty..4ty+3
    const int node_base = blockIdx.x * TILE_N;

    // stage W (row-major [128][64] floats == [128][32] f32x2 pairs)
    {
        const float4* W4  = reinterpret_cast<const float4*>(W);
        float4* Wp4 = reinterpret_cast<float4*>(Wp);
        #pragma unroll
        for (int i = tid; i < 128 * 64 / 4; i += 256) Wp4[i] = W4[i];
    }

    // stage A transposed: Ash[k][n] = concat(x, nsum)[node_base+n][k]
    {
        const float4* nsum4 = reinterpret_cast<const float4*>(g_nsum);
        #pragma unroll
        for (int it = 0; it < 8; it++) {
            int idx = it * 256 + tid;
            int n = idx & 63;          // lanes consecutive in n -> STS conflict-free
            int r = idx >> 6;          // k-quad 0..31
            int gn = node_base + n;
            float4 v = make_float4(0.f, 0.f, 0.f, 0.f);
            if (gn < n_nodes)
                v = (r < 16) ? x4[(long long)gn * 16 + r]
                             : nsum4[(long long)gn * 16 + (r - 16)];
            int k0 = 4 * r;
            Ash[(k0 + 0) * 64 + n] = v.x;
            Ash[(k0 + 1) * 64 + n] = v.y;
            Ash[(k0 + 2) * 64 + n] = v.z;
            Ash[(k0 + 3) * 64 + n] = v.w;
        }
    }
    __syncthreads();

    unsigned long long acc[4][2];
    #pragma unroll
    for (int i = 0; i < 4; i++) { acc[i][0] = 0ull; acc[i][1] = 0ull; }

    const float* ab = Ash + 4 * ty;
    const unsigned long long* wb = Wp + 2 * tx;

    #pragma unroll 8
    for (int k = 0; k < 128; k++) {
        float4 a = *reinterpret_cast<const float4*>(ab + k * 64);
        ulonglong2 w = *reinterpret_cast<const ulonglong2*>(wb + k * 32);
        unsigned long long ap0, ap1, ap2, ap3;
        asm("mov.b64 %0, {%1, %1};" : "=l"(ap0) : "f"(a.x));
        asm("mov.b64 %0, {%1, %1};" : "=l"(ap1) : "f"(a.y));
        asm("mov.b64 %0, {%1, %1};" : "=l"(ap2) : "f"(a.z));
        asm("mov.b64 %0, {%1, %1};" : "=l"(ap3) : "f"(a.w));
        asm("fma.rn.f32x2 %0, %1, %2, %0;" : "+l"(acc[0][0]) : "l"(ap0), "l"(w.x));
        asm("fma.rn.f32x2 %0, %1, %2, %0;" : "+l"(acc[0][1]) : "l"(ap0), "l"(w.y));
        asm("fma.rn.f32x2 %0, %1, %2, %0;" : "+l"(acc[1][0]) : "l"(ap1), "l"(w.x));
        asm("fma.rn.f32x2 %0, %1, %2, %0;" : "+l"(acc[1][1]) : "l"(ap1), "l"(w.y));
        asm("fma.rn.f32x2 %0, %1, %2, %0;" : "+l"(acc[2][0]) : "l"(ap2), "l"(w.x));
        asm("fma.rn.f32x2 %0, %1, %2, %0;" : "+l"(acc[2][1]) : "l"(ap2), "l"(w.y));
        asm("fma.rn.f32x2 %0, %1, %2, %0;" : "+l"(acc[3][0]) : "l"(ap3), "l"(w.x));
        asm("fma.rn.f32x2 %0, %1, %2, %0;" : "+l"(acc[3][1]) : "l"(ap3), "l"(w.y));
    }

    // epilogue: bias + LayerNorm + store
    const float4 bj = reinterpret_cast<const float4*>(b)[tx];
    const float4 gj = reinterpret_cast<const float4*>(gamma)[tx];
    const float4 ej = reinterpret_cast<const float4*>(beta)[tx];

    float val[4][4];
    #pragma unroll
    for (int i = 0; i < 4; i++) {
        val[i][0] = __uint_as_float((unsigned)(acc[i][0] & 0xffffffffull)) + bj.x;
        val[i][1] = __uint_as_float((unsigned)(acc[i][0] >> 32))           + bj.y;
        val[i][2] = __uint_as_float((unsigned)(acc[i][1] & 0xffffffffull)) + bj.z;
        val[i][3] = __uint_as_float((unsigned)(acc[i][1] >> 32))           + bj.w;
    }

    float s[4], ss[4];
    #pragma unroll
    for (int i = 0; i < 4; i++) {
        s[i]  = val[i][0] + val[i][1] + val[i][2] + val[i][3];
        ss[i] = val[i][0] * val[i][0] + val[i][1] * val[i][1]
              + val[i][2] * val[i][2] + val[i][3] * val[i][3];
    }
    // reduce across the 16 tx lanes (xor masks stay inside each 16-lane half)
    #pragma unroll
    for (int m = 1; m < 16; m <<= 1) {
        #pragma unroll
        for (int i = 0; i < 4; i++) {
            s[i]  += __shfl_xor_sync(0xFFFFFFFFu, s[i],  m);
            ss[i] += __shfl_xor_sync(0xFFFFFFFFu, ss[i], m);
        }
    }

    const float inv64 = 1.0f / 64.0f;
    #pragma unroll
    for (int i = 0; i < 4; i++) {
        float mu  = s[i] * inv64;
        float var = ss[i] * inv64 - mu * mu;
        float rs  = rsqrtf(var + LN_EPS);
        int gn = node_base + 4 * ty + i;
        if (gn < n_nodes) {
            float4 o;
            o.x = (val[i][0] - mu) * rs * gj.x + ej.x;
            o.y = (val[i][1] - mu) * rs * gj.y + ej.y;
            o.z = (val[i][2] - mu) * rs * gj.z + ej.z;
            o.w = (val[i][3] - mu) * rs * gj.w + ej.w;
            out4[(long long)gn * 16 + tx] = o;
        }
    }
}

// ---------------------------------------------------------------------------
// launch
// ---------------------------------------------------------------------------
extern "C" void kernel_launch(void* const* d_in, const int* in_sizes, int n_in,
                              void* d_out, int out_size) {
    const float* x     = (const float*)d_in[0];
    const void*  ei    = d_in[1];
    const float* W     = (const float*)d_in[2];
    const float* b     = (const float*)d_in[3];
    const float* gamma = (const float*)d_in[4];
    const float* beta  = (const float*)d_in[5];
    float* out = (float*)d_out;

    const int n_nodes = in_sizes[0] / D;      // 100000
    const int n_edges = in_sizes[1] / 2;      // 1000000

    // dynamic smem: A (32KB) + W pairs (32KB) = 64KB > 48KB default
    static_assert(128 * 64 * 4 + 128 * 32 * 8 == 65536, "smem layout");
    cudaFuncSetAttribute(gemm_ln_kernel,
                         cudaFuncAttributeMaxDynamicSharedMemorySize, 65536);

    // 0a: dtype detection
    int n_words = n_edges / 2;
    if (n_words > 256) n_words = 256;
    detect_dtype_kernel<<<1, 32>>>((const long long*)ei, n_words, n_nodes);

    // 0b: zero accumulator
    const int n_f4 = n_nodes * D / 4;
    zero_kernel<<<1184, 256>>>(n_f4);

    // 1: scatter
    scatter_kernel<<<2368, 256>>>((const float2*)x, ei, n_edges);

    // 2: fused GEMM + LayerNorm (register-tiled, FFMA2)
    int gemm_blocks = (n_nodes + TILE_N - 1) / TILE_N;
    gemm_ln_kernel<<<gemm_blocks, 256, 65536>>>(
        (const float4*)x, W, b, gamma, beta, (float4*)out, n_nodes);
}

// round 3
// speedup vs baseline: 1.9143x; 1.1334x over previous
#include <cuda_runtime.h>
#include <cuda_bf16.h>
#include <cstdint>

// Problem constants (shapes fixed by the dataset)
#define N_NODES_MAX 100000
#define D 64
#define OUT 64
#define LN_EPS 1e-5f

// Scratch: neighbor_sum accumulator [N, D] — device global (no allocs allowed)
__device__ __align__(16) float g_nsum[N_NODES_MAX * D];
__device__ int g_is64;  // 1 if edge_index is int64, 0 if int32

// ---------------------------------------------------------------------------
// Kernel 0: zero the accumulator + (block 0) parallel dtype detection.
// Detection: if data is int32 pairs read as int64, high halves are ~uniform
// node indices; P(all 256 words look like valid int64) ~ 1e-1280.
// ---------------------------------------------------------------------------
__global__ void zero_detect_kernel(int n_float4,
                                   const long long* __restrict__ ei,
                                   int n_words, int n_nodes) {
    if (blockIdx.x == 0) {
        int bad = 0;
        int i = threadIdx.x;
        if (i < n_words) {
            long long v = ei[i];
            bad = (v < 0 || v >= (long long)n_nodes) ? 1 : 0;
        }
        int any_bad = __syncthreads_or(bad);
        if (threadIdx.x == 0) g_is64 = any_bad ? 0 : 1;
    }
    int i = blockIdx.x * blockDim.x + threadIdx.x;
    int stride = gridDim.x * blockDim.x;
    float4* p = reinterpret_cast<float4*>(g_nsum);
    float4 z = make_float4(0.f, 0.f, 0.f, 0.f);
    for (; i < n_float4; i += stride) p[i] = z;
}

// ---------------------------------------------------------------------------
// Kernel 1: scatter-add. 16 lanes per edge; lane handles float4 chunk `sub`.
// red.global.add.v4.f32: 4 floats per instruction, no return value.
// ---------------------------------------------------------------------------
__global__ void scatter_kernel(const float4* __restrict__ x4,
                               const void* __restrict__ ei_raw,
                               int n_edges) {
    const int t   = blockIdx.x * blockDim.x + threadIdx.x;
    const int sub = t & 15;
    int e = t >> 4;
    const int estride = (gridDim.x * blockDim.x) >> 4;
    const int is64 = g_is64;
    float4* __restrict__ nsum4 = reinterpret_cast<float4*>(g_nsum);

    const long long* ei64 = reinterpret_cast<const long long*>(ei_raw);
    const int*       ei32 = reinterpret_cast<const int*>(ei_raw);

    for (; e < n_edges; e += estride) {
        long long row, col;
        if (is64) {
            row = ei64[e];
            col = ei64[n_edges + e];
        } else {
            row = ei32[e];
            col = ei32[n_edges + e];
        }
        float4 v = x4[row * 16 + sub];
        float4* dst = &nsum4[col * 16 + sub];
        asm volatile("red.global.add.v4.f32 [%0], {%1, %2, %3, %4};"
                     :: "l"(dst), "f"(v.x), "f"(v.y), "f"(v.z), "f"(v.w)
                     : "memory");
    }
}

// ---------------------------------------------------------------------------
// Kernel 2: fused concat + Linear(128->64) + bias + LayerNorm.
// Register-tiled GEMM: block = 128 nodes x 64 outs, 256 threads,
// thread tile = 8 nodes x 4 outs, K = 128.
// A staged transposed [k][n] (64KB); W staged as f32x2 pairs (32KB).
// Inner loop per k per thread:
//   2x LDS.128 (a: 8 nodes, broadcast-dedup'd across warp)
//   1x LDS.128 (w: 2 f32x2 pairs)
//   8x mov.b64 {a,a}  +  16x fma.rn.f32x2  (32 FMA lanes)
// LayerNorm via 4-round shfl.xor over the 16 tx lanes.
// ---------------------------------------------------------------------------
#define TILE_N 128

__global__ void __launch_bounds__(256, 2) gemm_ln_kernel(
    const float4* __restrict__ x4,
    const float*  __restrict__ W,
    const float*  __restrict__ b,
    const float*  __restrict__ gamma,
    const float*  __restrict__ beta,
    float4* __restrict__ out4,
    int n_nodes) {

    extern __shared__ char smem_raw[];
    float* Ash = reinterpret_cast<float*>(smem_raw);                       // [128][128]
    unsigned long long* Wp =
        reinterpret_cast<unsigned long long*>(smem_raw + 128 * 128 * 4);   // [128][32]

    const int tid = threadIdx.x;
    const int tx  = tid & 15;   // out-pair group: outs 4tx..4tx+3
    const int ty  = tid >> 4;   // node group: nodes 8ty..8ty+7
    const int node_base = blockIdx.x * TILE_N;

    // stage W (row-major [128][64] floats == [128][32] f32x2 pairs)
    {
        const float4* W4  = reinterpret_cast<const float4*>(W);
        float4* Wp4 = reinterpret_cast<float4*>(Wp);
        #pragma unroll
        for (int i = tid; i < 128 * 64 / 4; i += 256) Wp4[i] = W4[i];
    }

    // stage A transposed: Ash[k][n] = concat(x, nsum)[node_base+n][k]
    {
        const float4* nsum4 = reinterpret_cast<const float4*>(g_nsum);
        #pragma unroll
        for (int it = 0; it < 16; it++) {
            int idx = it * 256 + tid;
            int n = idx & 127;         // lanes consecutive in n -> STS conflict-free
            int r = idx >> 7;          // k-quad 0..31
            int gn = node_base + n;
            float4 v = make_float4(0.f, 0.f, 0.f, 0.f);
            if (gn < n_nodes)
                v = (r < 16) ? x4[(long long)gn * 16 + r]
                             : nsum4[(long long)gn * 16 + (r - 16)];
            int k0 = 4 * r;
            Ash[(k0 + 0) * 128 + n] = v.x;
            Ash[(k0 + 1) * 128 + n] = v.y;
            Ash[(k0 + 2) * 128 + n] = v.z;
            Ash[(k0 + 3) * 128 + n] = v.w;
        }
    }
    __syncthreads();

    unsigned long long acc[8][2];
    #pragma unroll
    for (int i = 0; i < 8; i++) { acc[i][0] = 0ull; acc[i][1] = 0ull; }

    const float* ab = Ash + 8 * ty;
    const unsigned long long* wb = Wp + 2 * tx;

    #pragma unroll 8
    for (int k = 0; k < 128; k++) {
        float4 a0 = *reinterpret_cast<const float4*>(ab + k * 128);
        float4 a1 = *reinterpret_cast<const float4*>(ab + k * 128 + 4);
        ulonglong2 w = *reinterpret_cast<const ulonglong2*>(wb + k * 32);
        unsigned long long ap[8];
        asm("mov.b64 %0, {%1, %1};" : "=l"(ap[0]) : "f"(a0.x));
        asm("mov.b64 %0, {%1, %1};" : "=l"(ap[1]) : "f"(a0.y));
        asm("mov.b64 %0, {%1, %1};" : "=l"(ap[2]) : "f"(a0.z));
        asm("mov.b64 %0, {%1, %1};" : "=l"(ap[3]) : "f"(a0.w));
        asm("mov.b64 %0, {%1, %1};" : "=l"(ap[4]) : "f"(a1.x));
        asm("mov.b64 %0, {%1, %1};" : "=l"(ap[5]) : "f"(a1.y));
        asm("mov.b64 %0, {%1, %1};" : "=l"(ap[6]) : "f"(a1.z));
        asm("mov.b64 %0, {%1, %1};" : "=l"(ap[7]) : "f"(a1.w));
        #pragma unroll
        for (int i = 0; i < 8; i++) {
            asm("fma.rn.f32x2 %0, %1, %2, %0;" : "+l"(acc[i][0]) : "l"(ap[i]), "l"(w.x));
            asm("fma.rn.f32x2 %0, %1, %2, %0;" : "+l"(acc[i][1]) : "l"(ap[i]), "l"(w.y));
        }
    }

    // epilogue: bias + LayerNorm + store
    const float4 bj = reinterpret_cast<const float4*>(b)[tx];
    const float4 gj = reinterpret_cast<const float4*>(gamma)[tx];
    const float4 ej = reinterpret_cast<const float4*>(beta)[tx];

    float val[8][4];
    #pragma unroll
    for (int i = 0; i < 8; i++) {
        val[i][0] = __uint_as_float((unsigned)(acc[i][0] & 0xffffffffull)) + bj.x;
        val[i][1] = __uint_as_float((unsigned)(acc[i][0] >> 32))           + bj.y;
        val[i][2] = __uint_as_float((unsigned)(acc[i][1] & 0xffffffffull)) + bj.z;
        val[i][3] = __uint_as_float((unsigned)(acc[i][1] >> 32))           + bj.w;
    }

    float s[8], ss[8];
    #pragma unroll
    for (int i = 0; i < 8; i++) {
        s[i]  = val[i][0] + val[i][1] + val[i][2] + val[i][3];
        ss[i] = val[i][0] * val[i][0] + val[i][1] * val[i][1]
              + val[i][2] * val[i][2] + val[i][3] * val[i][3];
    }
    // reduce across the 16 tx lanes (xor masks stay inside each 16-lane half)
    #pragma unroll
    for (int m = 1; m < 16; m <<= 1) {
        #pragma unroll
        for (int i = 0; i < 8; i++) {
            s[i]  += __shfl_xor_sync(0xFFFFFFFFu, s[i],  m);
            ss[i] += __shfl_xor_sync(0xFFFFFFFFu, ss[i], m);
        }
    }

    const float inv64 = 1.0f / 64.0f;
    #pragma unroll
    for (int i = 0; i < 8; i++) {
        float mu  = s[i] * inv64;
        float var = ss[i] * inv64 - mu * mu;
        float rs  = rsqrtf(var + LN_EPS);
        int gn = node_base + 8 * ty + i;
        if (gn < n_nodes) {
            float4 o;
            o.x = (val[i][0] - mu) * rs * gj.x + ej.x;
            o.y = (val[i][1] - mu) * rs * gj.y + ej.y;
            o.z = (val[i][2] - mu) * rs * gj.z + ej.z;
            o.w = (val[i][3] - mu) * rs * gj.w + ej.w;
            out4[(long long)gn * 16 + tx] = o;
        }
    }
}

// ---------------------------------------------------------------------------
// launch
// ---------------------------------------------------------------------------
extern "C" void kernel_launch(void* const* d_in, const int* in_sizes, int n_in,
                              void* d_out, int out_size) {
    const float* x     = (const float*)d_in[0];
    const void*  ei    = d_in[1];
    const float* W     = (const float*)d_in[2];
    const float* b     = (const float*)d_in[3];
    const float* gamma = (const float*)d_in[4];
    const float* beta  = (const float*)d_in[5];
    float* out = (float*)d_out;

    const int n_nodes = in_sizes[0] / D;      // 100000
    const int n_edges = in_sizes[1] / 2;      // 1000000

    // dynamic smem: A (64KB) + W pairs (32KB) = 96KB
    static_assert(128 * 128 * 4 + 128 * 32 * 8 == 98304, "smem layout");
    cudaFuncSetAttribute(gemm_ln_kernel,
                         cudaFuncAttributeMaxDynamicSharedMemorySize, 98304);

    // 0: zero accumulator + parallel dtype detection (block 0)
    int n_words = n_edges / 2;
    if (n_words > 256) n_words = 256;
    const int n_f4 = n_nodes * D / 4;
    zero_detect_kernel<<<1184, 256>>>(n_f4, (const long long*)ei, n_words, n_nodes);

    // 1: scatter (16 lanes/edge, vectorized red.v4)
    scatter_kernel<<<2368, 256>>>((const float4*)x, ei, n_edges);

    // 2: fused GEMM + LayerNorm (register-tiled, FFMA2, 8x4 thread tile)
    int gemm_blocks = (n_nodes + TILE_N - 1) / TILE_N;
    gemm_ln_kernel<<<gemm_blocks, 256, 98304>>>(
        (const float4*)x, W, b, gamma, beta, (float4*)out, n_nodes);
}